// round 6
// baseline (speedup 1.0000x reference)
#include <cuda_runtime.h>
#include <math.h>

#define Bb   4
#define Tdim 2048
#define Cdim 2048
#define BT   8192        // Bb*Tdim
#define H    16
#define HD   128
#define Rr   128
#define NB   16
#define BS   128
#define NBH  64          // Bb*H

static const float SCALE_ATT = 0.08838834764831845f; // 1/sqrt(128)
#define FULLM 0xffffffffu

// scratch (device globals: no allocation allowed)
__device__ float g_t[(size_t)BT * Rr];
__device__ float g_q[(size_t)Bb * Tdim * Cdim];
__device__ float g_k[(size_t)Bb * Tdim * Cdim];
__device__ float g_v[(size_t)Bb * Tdim * Cdim];
__device__ float g_y[(size_t)Bb * Tdim * Cdim];

// ---------------------------------------------------------------------------
// tf32 mma helpers
// ---------------------------------------------------------------------------
__device__ __forceinline__ unsigned f2tf32(float f) {
    unsigned r;
    asm("cvt.rna.tf32.f32 %0, %1;" : "=r"(r) : "f"(f));
    return r;
}

__device__ __forceinline__ void mma_tf32(float* c, const unsigned* a, const unsigned* b) {
    asm volatile(
        "mma.sync.aligned.m16n8k8.row.col.f32.tf32.tf32.f32 "
        "{%0,%1,%2,%3}, {%4,%5,%6,%7}, {%8,%9}, {%0,%1,%2,%3};\n"
        : "+f"(c[0]), "+f"(c[1]), "+f"(c[2]), "+f"(c[3])
        : "r"(a[0]), "r"(a[1]), "r"(a[2]), "r"(a[3]), "r"(b[0]), "r"(b[1]));
}

// A tile: 128 rows x 32 k, row-major source with leading dim ld (pre-offset ptr)
__device__ __forceinline__ void load_A(const float* __restrict__ A, int ld, int tid,
                                       unsigned (*As)[36]) {
#pragma unroll
    for (int p = 0; p < 4; p++) {
        int idx = tid + p * 256;
        int row = idx >> 3, c4 = (idx & 7) << 2;
        float4 v = *(const float4*)(A + (size_t)row * ld + c4);
        As[row][c4 + 0] = f2tf32(v.x); As[row][c4 + 1] = f2tf32(v.y);
        As[row][c4 + 2] = f2tf32(v.z); As[row][c4 + 3] = f2tf32(v.w);
    }
}

// B tile from weight stored [k][n] (32 x 128), direct into k-major Bs[k][n]
__device__ __forceinline__ void load_B_kn(const float* __restrict__ B, int ld, int tid,
                                          unsigned (*Bs)[132]) {
#pragma unroll
    for (int p = 0; p < 4; p++) {
        int idx = tid + p * 256;
        int kr = idx >> 5, n4 = (idx & 31) << 2;
        float4 v = *(const float4*)(B + (size_t)kr * ld + n4);
        Bs[kr][n4 + 0] = f2tf32(v.x); Bs[kr][n4 + 1] = f2tf32(v.y);
        Bs[kr][n4 + 2] = f2tf32(v.z); Bs[kr][n4 + 3] = f2tf32(v.w);
    }
}

// B tile from weight stored [n][k] (128 n x 32 k), transpose into Bs[k][n]
__device__ __forceinline__ void load_B_nk(const float* __restrict__ B, int ld, int tid,
                                          unsigned (*Bs)[132]) {
#pragma unroll
    for (int p = 0; p < 4; p++) {
        int idx = tid + p * 256;
        int n = idx >> 3, k4 = (idx & 7) << 2;
        float4 v = *(const float4*)(B + (size_t)n * ld + k4);
        Bs[k4 + 0][n] = f2tf32(v.x); Bs[k4 + 1][n] = f2tf32(v.y);
        Bs[k4 + 2][n] = f2tf32(v.z); Bs[k4 + 3][n] = f2tf32(v.w);
    }
}

// 8 warps: warp tile 64x32 inside 128x128 block tile; 4 k-substeps of 8
__device__ __forceinline__ void mma_tile_compute(const unsigned (*As)[36],
                                                 const unsigned (*Bs)[132],
                                                 int wm, int wn, int lane,
                                                 float acc[4][4][4]) {
    int g = lane >> 2, tg = lane & 3;
#pragma unroll
    for (int kk = 0; kk < 4; kk++) {
        int k = kk * 8;
        unsigned a[4][4], b[4][2];
#pragma unroll
        for (int im = 0; im < 4; im++) {
            int mb = wm * 64 + im * 16;
            a[im][0] = As[mb + g][k + tg];
            a[im][1] = As[mb + g + 8][k + tg];
            a[im][2] = As[mb + g][k + tg + 4];
            a[im][3] = As[mb + g + 8][k + tg + 4];
        }
#pragma unroll
        for (int jn = 0; jn < 4; jn++) {
            int nb = wn * 32 + jn * 8;
            b[jn][0] = Bs[k + tg][nb + g];
            b[jn][1] = Bs[k + tg + 4][nb + g];
        }
#pragma unroll
        for (int im = 0; im < 4; im++)
#pragma unroll
            for (int jn = 0; jn < 4; jn++)
                mma_tf32(acc[im][jn], a[im], b[jn]);
    }
}

// ---------------------------------------------------------------------------
// K1: t = X @ L^T   (M=8192, N=128, K=2048)
// ---------------------------------------------------------------------------
__global__ __launch_bounds__(256) void left_proj_mma(const float* __restrict__ X,
                                                     const float* __restrict__ L,
                                                     float* __restrict__ Tout) {
    __shared__ unsigned As[128][36];
    __shared__ unsigned Bs[32][132];
    int tid = threadIdx.x, lane = tid & 31, w = tid >> 5, wm = w >> 2, wn = w & 3;
    int m0 = blockIdx.x * 128;
    float acc[4][4][4] = {};
    for (int k0 = 0; k0 < Cdim; k0 += 32) {
        load_A(X + (size_t)m0 * Cdim + k0, Cdim, tid, As);
        load_B_nk(L + k0, Cdim, tid, Bs);
        __syncthreads();
        mma_tile_compute(As, Bs, wm, wn, lane, acc);
        __syncthreads();
    }
    int g = lane >> 2, tg = lane & 3;
#pragma unroll
    for (int im = 0; im < 4; im++)
#pragma unroll
        for (int jn = 0; jn < 4; jn++) {
            int r = m0 + wm * 64 + im * 16 + g;
            int c = wn * 32 + jn * 8 + tg * 2;
            Tout[(size_t)r * Rr + c]           = acc[im][jn][0];
            Tout[(size_t)r * Rr + c + 1]       = acc[im][jn][1];
            Tout[(size_t)(r + 8) * Rr + c]     = acc[im][jn][2];
            Tout[(size_t)(r + 8) * Rr + c + 1] = acc[im][jn][3];
        }
}

// ---------------------------------------------------------------------------
// K2: fused LORI output (blockdiag + low-rank + biases)
// grid = (BT/128, NB)
// ---------------------------------------------------------------------------
__global__ __launch_bounds__(256) void fused_out_mma(const float* __restrict__ X,
                                                     const float* __restrict__ Tl,
                                                     const float* __restrict__ Dg,
                                                     const float* __restrict__ RW,
                                                     const float* __restrict__ rb,
                                                     const float* __restrict__ bp,
                                                     float* __restrict__ Y) {
    __shared__ unsigned As[128][36];
    __shared__ unsigned Bs[32][132];
    int tid = threadIdx.x, lane = tid & 31, w = tid >> 5, wm = w >> 2, wn = w & 3;
    int m0 = blockIdx.x * 128;
    int nb = blockIdx.y;
    int c0 = nb * BS;
    const float* D = Dg + (size_t)nb * BS * BS;
    float acc[4][4][4] = {};

    // phase 1: block-diagonal, K = 128 (D stored [k][n])
    for (int k0 = 0; k0 < BS; k0 += 32) {
        load_A(X + (size_t)m0 * Cdim + c0 + k0, Cdim, tid, As);
        load_B_kn(D + (size_t)k0 * BS, BS, tid, Bs);
        __syncthreads();
        mma_tile_compute(As, Bs, wm, wn, lane, acc);
        __syncthreads();
    }
    // phase 2: low-rank, K = 128 (RW stored [n][k])
    for (int k0 = 0; k0 < Rr; k0 += 32) {
        load_A(Tl + (size_t)m0 * Rr + k0, Rr, tid, As);
        load_B_nk(RW + (size_t)c0 * Rr + k0, Rr, tid, Bs);
        __syncthreads();
        mma_tile_compute(As, Bs, wm, wn, lane, acc);
        __syncthreads();
    }

    int g = lane >> 2, tg = lane & 3;
#pragma unroll
    for (int im = 0; im < 4; im++)
#pragma unroll
        for (int jn = 0; jn < 4; jn++) {
            int r = m0 + wm * 64 + im * 16 + g;
            int cl = wn * 32 + jn * 8 + tg * 2;
            int c = c0 + cl;
            float b0 = rb[c] + bp[c], b1 = rb[c + 1] + bp[c + 1];
            Y[(size_t)r * Cdim + c]           = acc[im][jn][0] + b0;
            Y[(size_t)r * Cdim + c + 1]       = acc[im][jn][1] + b1;
            Y[(size_t)(r + 8) * Cdim + c]     = acc[im][jn][2] + b0;
            Y[(size_t)(r + 8) * Cdim + c + 1] = acc[im][jn][3] + b1;
        }
}

// ---------------------------------------------------------------------------
// K3: fused flash attention (tf32 mma, fp32 accum, online softmax)
// grid = (qt=16, bh=64), block = 256 (8 warps, each owns 16 q-rows)
// ---------------------------------------------------------------------------
#define QS_LD 132
#define BS_LD 136
#define FA_SMEM ((128 * QS_LD + 32 * BS_LD) * 4)

__global__ __launch_bounds__(256) void flash_attn(const float* __restrict__ Q,
                                                  const float* __restrict__ Kg,
                                                  const float* __restrict__ Vg,
                                                  float* __restrict__ Y) {
    extern __shared__ unsigned fa_smem[];
    unsigned (*Qs)[QS_LD] = (unsigned(*)[QS_LD])fa_smem;
    unsigned (*Cs)[BS_LD] = (unsigned(*)[BS_LD])(fa_smem + 128 * QS_LD);

    int qt = gridDim.x - 1 - blockIdx.x;   // big q-tiles first (load balance)
    int bh = blockIdx.y;
    int b = bh / H, h = bh % H;
    const float* Qp = Q  + (size_t)b * Tdim * Cdim + (size_t)h * HD;
    const float* Kp = Kg + (size_t)b * Tdim * Cdim + (size_t)h * HD;
    const float* Vp = Vg + (size_t)b * Tdim * Cdim + (size_t)h * HD;
    float* Yp       = Y  + (size_t)b * Tdim * Cdim + (size_t)h * HD;

    int tid = threadIdx.x, lane = tid & 31, w = tid >> 5;
    int g = lane >> 2, tg = lane & 3;
    int qr = w * 16;                 // warp's local q-row base within tile

    // load Q tile (128 x 128) -> tf32 smem
    for (int i = tid; i < 128 * 32; i += 256) {
        int row = i >> 5, c4 = (i & 31) << 2;
        float4 v = *(const float4*)(Qp + (size_t)(qt * 128 + row) * Cdim + c4);
        Qs[row][c4 + 0] = f2tf32(v.x); Qs[row][c4 + 1] = f2tf32(v.y);
        Qs[row][c4 + 2] = f2tf32(v.z); Qs[row][c4 + 3] = f2tf32(v.w);
    }

    float acco[16][4] = {};          // O accumulator: 16 hd-nblocks
    float m0 = -1e30f, m1 = -1e30f;  // running row max (rows g, g+8)
    float l0 = 0.f, l1 = 0.f;        // running row sum

    for (int kt = 0; kt <= qt; kt++) {
        // ---- S = Q @ K^T over this key tile ----
        float accs[16][4] = {};
#pragma unroll 1
        for (int c = 0; c < 4; c++) {
            __syncthreads();
            // K chunk: keys n=0..127, hd cols c*32..+31, transposed -> Cs[k][n]
            for (int i = tid; i < 128 * 8; i += 256) {
                int n = i >> 3, k4 = (i & 7) << 2;
                float4 v = *(const float4*)(Kp + (size_t)(kt * 128 + n) * Cdim + c * 32 + k4);
                Cs[k4 + 0][n] = f2tf32(v.x); Cs[k4 + 1][n] = f2tf32(v.y);
                Cs[k4 + 2][n] = f2tf32(v.z); Cs[k4 + 3][n] = f2tf32(v.w);
            }
            __syncthreads();
#pragma unroll
            for (int kk = 0; kk < 4; kk++) {
                int kg = c * 32 + kk * 8;
                unsigned aq[4];
                aq[0] = Qs[qr + g][kg + tg];
                aq[1] = Qs[qr + g + 8][kg + tg];
                aq[2] = Qs[qr + g][kg + tg + 4];
                aq[3] = Qs[qr + g + 8][kg + tg + 4];
#pragma unroll
                for (int nb = 0; nb < 16; nb++) {
                    unsigned bb[2];
                    bb[0] = Cs[kk * 8 + tg][nb * 8 + g];
                    bb[1] = Cs[kk * 8 + tg + 4][nb * 8 + g];
                    mma_tf32(accs[nb], aq, bb);
                }
            }
        }

        // ---- scale + causal mask + online softmax ----
        bool diag = (kt == qt);
        int rl0 = qr + g, rl1 = qr + g + 8;    // local row indices
        float mx0 = -1e30f, mx1 = -1e30f;
#pragma unroll
        for (int nb = 0; nb < 16; nb++) {
            int cl = nb * 8 + 2 * tg;          // local col of elems 0/2
            float v0 = accs[nb][0] * SCALE_ATT;
            float v1 = accs[nb][1] * SCALE_ATT;
            float v2 = accs[nb][2] * SCALE_ATT;
            float v3 = accs[nb][3] * SCALE_ATT;
            if (diag) {
                if (cl     > rl0) v0 = -1e30f;
                if (cl + 1 > rl0) v1 = -1e30f;
                if (cl     > rl1) v2 = -1e30f;
                if (cl + 1 > rl1) v3 = -1e30f;
            }
            accs[nb][0] = v0; accs[nb][1] = v1; accs[nb][2] = v2; accs[nb][3] = v3;
            mx0 = fmaxf(mx0, fmaxf(v0, v1));
            mx1 = fmaxf(mx1, fmaxf(v2, v3));
        }
        // quad reduction (lanes sharing g)
        mx0 = fmaxf(mx0, __shfl_xor_sync(FULLM, mx0, 1));
        mx0 = fmaxf(mx0, __shfl_xor_sync(FULLM, mx0, 2));
        mx1 = fmaxf(mx1, __shfl_xor_sync(FULLM, mx1, 1));
        mx1 = fmaxf(mx1, __shfl_xor_sync(FULLM, mx1, 2));

        float mn0 = fmaxf(m0, mx0), mn1 = fmaxf(m1, mx1);
        float sc0 = __expf(m0 - mn0), sc1 = __expf(m1 - mn1);
        m0 = mn0; m1 = mn1;
        float s0 = 0.f, s1 = 0.f;
#pragma unroll
        for (int nb = 0; nb < 16; nb++) {
            float p0 = __expf(accs[nb][0] - mn0);
            float p1 = __expf(accs[nb][1] - mn0);
            float p2 = __expf(accs[nb][2] - mn1);
            float p3 = __expf(accs[nb][3] - mn1);
            s0 += p0 + p1; s1 += p2 + p3;
            // store tf32 bit pattern in-place for PV mma
            accs[nb][0] = __uint_as_float(f2tf32(p0));
            accs[nb][1] = __uint_as_float(f2tf32(p1));
            accs[nb][2] = __uint_as_float(f2tf32(p2));
            accs[nb][3] = __uint_as_float(f2tf32(p3));
        }
        // FIX (round 5): quad-reduce the partial row sums — each thread only
        // holds 32 of the 128 columns; the normalizer is the FULL row sum.
        s0 += __shfl_xor_sync(FULLM, s0, 1);
        s0 += __shfl_xor_sync(FULLM, s0, 2);
        s1 += __shfl_xor_sync(FULLM, s1, 1);
        s1 += __shfl_xor_sync(FULLM, s1, 2);
        l0 = l0 * sc0 + s0; l1 = l1 * sc1 + s1;
#pragma unroll
        for (int nb = 0; nb < 16; nb++) {
            acco[nb][0] *= sc0; acco[nb][1] *= sc0;
            acco[nb][2] *= sc1; acco[nb][3] *= sc1;
        }

        // ---- O += P @ V ----
#pragma unroll 1
        for (int c = 0; c < 4; c++) {
            __syncthreads();
            // V chunk: keys kr = c*32..+31 (k), hd cols (n) -> Cs[k][n]
            for (int i = tid; i < 32 * 32; i += 256) {
                int kr = i >> 5, n4 = (i & 31) << 2;
                float4 v = *(const float4*)(Vp + (size_t)(kt * 128 + c * 32 + kr) * Cdim + n4);
                Cs[kr][n4 + 0] = f2tf32(v.x); Cs[kr][n4 + 1] = f2tf32(v.y);
                Cs[kr][n4 + 2] = f2tf32(v.z); Cs[kr][n4 + 3] = f2tf32(v.w);
            }
            __syncthreads();
#pragma unroll
            for (int kk = 0; kk < 4; kk++) {
                int kb = c * 4 + kk;  // S n-block == PV k-block
                // C-frag -> A-frag permutation via quad shuffles
                float c0 = accs[kb][0], c1 = accs[kb][1];
                float c2 = accs[kb][2], c3 = accs[kb][3];
                int q0 = (lane & ~3) | (tg >> 1);        // owner of col tg
                int q1 = q0 | 2;                          // owner of col tg+4
                bool odd = tg & 1;
                float t00 = __shfl_sync(FULLM, c0, q0), t01 = __shfl_sync(FULLM, c1, q0);
                float t10 = __shfl_sync(FULLM, c2, q0), t11 = __shfl_sync(FULLM, c3, q0);
                float t20 = __shfl_sync(FULLM, c0, q1), t21 = __shfl_sync(FULLM, c1, q1);
                float t30 = __shfl_sync(FULLM, c2, q1), t31 = __shfl_sync(FULLM, c3, q1);
                unsigned ap[4];
                ap[0] = __float_as_uint(odd ? t01 : t00);  // row g,   col tg
                ap[1] = __float_as_uint(odd ? t11 : t10);  // row g+8, col tg
                ap[2] = __float_as_uint(odd ? t21 : t20);  // row g,   col tg+4
                ap[3] = __float_as_uint(odd ? t31 : t30);  // row g+8, col tg+4
#pragma unroll
                for (int nb = 0; nb < 16; nb++) {
                    unsigned bb[2];
                    bb[0] = Cs[kk * 8 + tg][nb * 8 + g];
                    bb[1] = Cs[kk * 8 + tg + 4][nb * 8 + g];
                    mma_tf32(acco[nb], ap, bb);
                }
            }
        }
    }

    // ---- epilogue: O / l ----
    float inv0 = 1.0f / l0, inv1 = 1.0f / l1;
    int r0 = qt * 128 + qr + g, r1 = r0 + 8;
#pragma unroll
    for (int nb = 0; nb < 16; nb++) {
        int cc = nb * 8 + 2 * tg;
        float2 o0 = make_float2(acco[nb][0] * inv0, acco[nb][1] * inv0);
        float2 o1 = make_float2(acco[nb][2] * inv1, acco[nb][3] * inv1);
        *(float2*)(Yp + (size_t)r0 * Cdim + cc) = o0;
        *(float2*)(Yp + (size_t)r1 * Cdim + cc) = o1;
    }
}

// ---------------------------------------------------------------------------
extern "C" void kernel_launch(void* const* d_in, const int* in_sizes, int n_in,
                              void* d_out, int out_size) {
    const float* x    = (const float*)d_in[0];
    const float* diag = (const float*)d_in[1];
    const float* left = (const float*)d_in[2];
    const float* rw   = (const float*)d_in[3];
    const float* rb   = (const float*)d_in[4];
    const float* bp   = (const float*)d_in[5];
    float* out = (float*)d_out;

    float *pt, *pq, *pk, *pv, *py;
    cudaGetSymbolAddress((void**)&pt, g_t);
    cudaGetSymbolAddress((void**)&pq, g_q);
    cudaGetSymbolAddress((void**)&pk, g_k);
    cudaGetSymbolAddress((void**)&pv, g_v);
    cudaGetSymbolAddress((void**)&py, g_y);

    static bool attr_done = false;
    if (!attr_done) {
        cudaFuncSetAttribute(flash_attn, cudaFuncAttributeMaxDynamicSharedMemorySize,
                             FA_SMEM);
        attr_done = true;
    }

    float* dst[3] = {pq, pk, pv};
    for (int i = 0; i < 3; i++) {
        left_proj_mma<<<BT / 128, 256>>>(x, left + (size_t)i * Rr * Cdim, pt);
        fused_out_mma<<<dim3(BT / 128, NB), 256>>>(
            x, pt,
            diag + (size_t)i * NB * BS * BS,
            rw + (size_t)i * Cdim * Rr,
            rb + (size_t)i * Cdim,
            bp + (size_t)i * Cdim,
            dst[i]);
    }

    flash_attn<<<dim3(16, NBH), 256, FA_SMEM>>>(pq, pk, pv, py);

    left_proj_mma<<<BT / 128, 256>>>(py, left + (size_t)3 * Rr * Cdim, pt);
    fused_out_mma<<<dim3(BT / 128, NB), 256>>>(
        py, pt,
        diag + (size_t)3 * NB * BS * BS,
        rw + (size_t)3 * Cdim * Rr,
        rb + (size_t)3 * Cdim,
        bp + (size_t)3 * Cdim,
        out);
}

// round 8
// speedup vs baseline: 1.3918x; 1.3918x over previous
#include <cuda_runtime.h>
#include <math.h>

#define Bb   4
#define Tdim 2048
#define Cdim 2048
#define BT   8192        // Bb*Tdim
#define H    16
#define HD   128
#define Rr   128
#define NB   16
#define BS   128
#define NBH  64          // Bb*H

static const float SCALE_ATT = 0.08838834764831845f; // 1/sqrt(128)
#define FULLM 0xffffffffu

// scratch (device globals: no allocation allowed)
__device__ float g_t[(size_t)BT * Rr];
__device__ float g_q[(size_t)Bb * Tdim * Cdim];
__device__ float g_k[(size_t)Bb * Tdim * Cdim];
__device__ float g_v[(size_t)Bb * Tdim * Cdim];
__device__ float g_y[(size_t)Bb * Tdim * Cdim];

// ---------------------------------------------------------------------------
// tf32 mma helpers
// ---------------------------------------------------------------------------
__device__ __forceinline__ unsigned f2tf32(float f) {
    unsigned r;
    asm("cvt.rna.tf32.f32 %0, %1;" : "=r"(r) : "f"(f));
    return r;
}

__device__ __forceinline__ void mma_tf32(float* c, const unsigned* a, const unsigned* b) {
    asm volatile(
        "mma.sync.aligned.m16n8k8.row.col.f32.tf32.tf32.f32 "
        "{%0,%1,%2,%3}, {%4,%5,%6,%7}, {%8,%9}, {%0,%1,%2,%3};\n"
        : "+f"(c[0]), "+f"(c[1]), "+f"(c[2]), "+f"(c[3])
        : "r"(a[0]), "r"(a[1]), "r"(a[2]), "r"(a[3]), "r"(b[0]), "r"(b[1]));
}

// A tile: 128 rows x 32 k, row-major source with leading dim ld (pre-offset ptr)
__device__ __forceinline__ void load_A(const float* __restrict__ A, int ld, int tid,
                                       unsigned (*As)[36]) {
#pragma unroll
    for (int p = 0; p < 4; p++) {
        int idx = tid + p * 256;
        int row = idx >> 3, c4 = (idx & 7) << 2;
        float4 v = *(const float4*)(A + (size_t)row * ld + c4);
        As[row][c4 + 0] = f2tf32(v.x); As[row][c4 + 1] = f2tf32(v.y);
        As[row][c4 + 2] = f2tf32(v.z); As[row][c4 + 3] = f2tf32(v.w);
    }
}

// B tile from weight stored [k][n] (32 x 128), direct into k-major Bs[k][n]
__device__ __forceinline__ void load_B_kn(const float* __restrict__ B, int ld, int tid,
                                          unsigned (*Bs)[132]) {
#pragma unroll
    for (int p = 0; p < 4; p++) {
        int idx = tid + p * 256;
        int kr = idx >> 5, n4 = (idx & 31) << 2;
        float4 v = *(const float4*)(B + (size_t)kr * ld + n4);
        Bs[kr][n4 + 0] = f2tf32(v.x); Bs[kr][n4 + 1] = f2tf32(v.y);
        Bs[kr][n4 + 2] = f2tf32(v.z); Bs[kr][n4 + 3] = f2tf32(v.w);
    }
}

// B tile from weight stored [n][k] (128 n x 32 k), transpose into Bs[k][n]
__device__ __forceinline__ void load_B_nk(const float* __restrict__ B, int ld, int tid,
                                          unsigned (*Bs)[132]) {
#pragma unroll
    for (int p = 0; p < 4; p++) {
        int idx = tid + p * 256;
        int n = idx >> 3, k4 = (idx & 7) << 2;
        float4 v = *(const float4*)(B + (size_t)n * ld + k4);
        Bs[k4 + 0][n] = f2tf32(v.x); Bs[k4 + 1][n] = f2tf32(v.y);
        Bs[k4 + 2][n] = f2tf32(v.z); Bs[k4 + 3][n] = f2tf32(v.w);
    }
}

// 8 warps: warp tile 64x32 inside 128x128 block tile; 4 k-substeps of 8
__device__ __forceinline__ void mma_tile_compute(const unsigned (*As)[36],
                                                 const unsigned (*Bs)[132],
                                                 int wm, int wn, int lane,
                                                 float acc[4][4][4]) {
    int g = lane >> 2, tg = lane & 3;
#pragma unroll
    for (int kk = 0; kk < 4; kk++) {
        int k = kk * 8;
        unsigned a[4][4], b[4][2];
#pragma unroll
        for (int im = 0; im < 4; im++) {
            int mb = wm * 64 + im * 16;
            a[im][0] = As[mb + g][k + tg];
            a[im][1] = As[mb + g + 8][k + tg];
            a[im][2] = As[mb + g][k + tg + 4];
            a[im][3] = As[mb + g + 8][k + tg + 4];
        }
#pragma unroll
        for (int jn = 0; jn < 4; jn++) {
            int nb = wn * 32 + jn * 8;
            b[jn][0] = Bs[k + tg][nb + g];
            b[jn][1] = Bs[k + tg + 4][nb + g];
        }
#pragma unroll
        for (int im = 0; im < 4; im++)
#pragma unroll
            for (int jn = 0; jn < 4; jn++)
                mma_tf32(acc[im][jn], a[im], b[jn]);
    }
}

// ---------------------------------------------------------------------------
// K1: t = X @ L^T   (M=8192, N=128, K=2048)
// ---------------------------------------------------------------------------
__global__ __launch_bounds__(256) void left_proj_mma(const float* __restrict__ X,
                                                     const float* __restrict__ L,
                                                     float* __restrict__ Tout) {
    __shared__ unsigned As[128][36];
    __shared__ unsigned Bs[32][132];
    int tid = threadIdx.x, lane = tid & 31, w = tid >> 5, wm = w >> 2, wn = w & 3;
    int m0 = blockIdx.x * 128;
    float acc[4][4][4] = {};
    for (int k0 = 0; k0 < Cdim; k0 += 32) {
        load_A(X + (size_t)m0 * Cdim + k0, Cdim, tid, As);
        load_B_nk(L + k0, Cdim, tid, Bs);
        __syncthreads();
        mma_tile_compute(As, Bs, wm, wn, lane, acc);
        __syncthreads();
    }
    int g = lane >> 2, tg = lane & 3;
#pragma unroll
    for (int im = 0; im < 4; im++)
#pragma unroll
        for (int jn = 0; jn < 4; jn++) {
            int r = m0 + wm * 64 + im * 16 + g;
            int c = wn * 32 + jn * 8 + tg * 2;
            Tout[(size_t)r * Rr + c]           = acc[im][jn][0];
            Tout[(size_t)r * Rr + c + 1]       = acc[im][jn][1];
            Tout[(size_t)(r + 8) * Rr + c]     = acc[im][jn][2];
            Tout[(size_t)(r + 8) * Rr + c + 1] = acc[im][jn][3];
        }
}

// ---------------------------------------------------------------------------
// K2: fused LORI output (blockdiag + low-rank + biases)
// grid = (BT/128, NB)
// ---------------------------------------------------------------------------
__global__ __launch_bounds__(256) void fused_out_mma(const float* __restrict__ X,
                                                     const float* __restrict__ Tl,
                                                     const float* __restrict__ Dg,
                                                     const float* __restrict__ RW,
                                                     const float* __restrict__ rb,
                                                     const float* __restrict__ bp,
                                                     float* __restrict__ Y) {
    __shared__ unsigned As[128][36];
    __shared__ unsigned Bs[32][132];
    int tid = threadIdx.x, lane = tid & 31, w = tid >> 5, wm = w >> 2, wn = w & 3;
    int m0 = blockIdx.x * 128;
    int nb = blockIdx.y;
    int c0 = nb * BS;
    const float* D = Dg + (size_t)nb * BS * BS;
    float acc[4][4][4] = {};

    // phase 1: block-diagonal, K = 128 (D stored [k][n])
    for (int k0 = 0; k0 < BS; k0 += 32) {
        load_A(X + (size_t)m0 * Cdim + c0 + k0, Cdim, tid, As);
        load_B_kn(D + (size_t)k0 * BS, BS, tid, Bs);
        __syncthreads();
        mma_tile_compute(As, Bs, wm, wn, lane, acc);
        __syncthreads();
    }
    // phase 2: low-rank, K = 128 (RW stored [n][k])
    for (int k0 = 0; k0 < Rr; k0 += 32) {
        load_A(Tl + (size_t)m0 * Rr + k0, Rr, tid, As);
        load_B_nk(RW + (size_t)c0 * Rr + k0, Rr, tid, Bs);
        __syncthreads();
        mma_tile_compute(As, Bs, wm, wn, lane, acc);
        __syncthreads();
    }

    int g = lane >> 2, tg = lane & 3;
#pragma unroll
    for (int im = 0; im < 4; im++)
#pragma unroll
        for (int jn = 0; jn < 4; jn++) {
            int r = m0 + wm * 64 + im * 16 + g;
            int cl = wn * 32 + jn * 8 + tg * 2;
            int c = c0 + cl;
            float b0 = rb[c] + bp[c], b1 = rb[c + 1] + bp[c + 1];
            Y[(size_t)r * Cdim + c]           = acc[im][jn][0] + b0;
            Y[(size_t)r * Cdim + c + 1]       = acc[im][jn][1] + b1;
            Y[(size_t)(r + 8) * Cdim + c]     = acc[im][jn][2] + b0;
            Y[(size_t)(r + 8) * Cdim + c + 1] = acc[im][jn][3] + b1;
        }
}

// ---------------------------------------------------------------------------
// K3: fused flash attention, WHOLE K and V tiles resident in smem.
// grid = (qt=16, bh=64), block = 256 (8 warps, each owns 16 q-rows)
// smem: Qs[128][132] + KT[128][132] + Vs[128][132] tf32  (~198 KB)
// Only 2 __syncthreads per key-tile (vs 16 in the chunked version).
// ---------------------------------------------------------------------------
#define FA_LD 132
#define FA_SMEM (3 * 128 * FA_LD * 4)

__global__ __launch_bounds__(256) void flash_attn(const float* __restrict__ Q,
                                                  const float* __restrict__ Kg,
                                                  const float* __restrict__ Vg,
                                                  float* __restrict__ Y) {
    extern __shared__ unsigned fa_smem[];
    unsigned (*Qs)[FA_LD] = (unsigned(*)[FA_LD])fa_smem;                    // [q][hd]
    unsigned (*KT)[FA_LD] = (unsigned(*)[FA_LD])(fa_smem + 128 * FA_LD);    // [hd][key]
    unsigned (*Vs)[FA_LD] = (unsigned(*)[FA_LD])(fa_smem + 2 * 128 * FA_LD);// [key][hd]

    int qt = gridDim.x - 1 - blockIdx.x;   // big q-tiles first (load balance)
    int bh = blockIdx.y;
    int b = bh / H, h = bh % H;
    const float* Qp = Q  + (size_t)b * Tdim * Cdim + (size_t)h * HD;
    const float* Kp = Kg + (size_t)b * Tdim * Cdim + (size_t)h * HD;
    const float* Vp = Vg + (size_t)b * Tdim * Cdim + (size_t)h * HD;
    float* Yp       = Y  + (size_t)b * Tdim * Cdim + (size_t)h * HD;

    int tid = threadIdx.x, lane = tid & 31, w = tid >> 5;
    int g = lane >> 2, tg = lane & 3;
    int qr = w * 16;                 // warp's local q-row base within tile

    // load Q tile (128 x 128) -> tf32 smem
    for (int i = tid; i < 128 * 32; i += 256) {
        int row = i >> 5, c4 = (i & 31) << 2;
        float4 v = *(const float4*)(Qp + (size_t)(qt * 128 + row) * Cdim + c4);
        Qs[row][c4 + 0] = f2tf32(v.x); Qs[row][c4 + 1] = f2tf32(v.y);
        Qs[row][c4 + 2] = f2tf32(v.z); Qs[row][c4 + 3] = f2tf32(v.w);
    }

    float acco[16][4] = {};          // O accumulator: 16 hd-nblocks
    float m0 = -1e30f, m1 = -1e30f;  // running row max (rows g, g+8)
    float l0 = 0.f, l1 = 0.f;        // running row sum

    for (int kt = 0; kt <= qt; kt++) {
        // ---- load whole K tile (transposed) and V tile ----
        __syncthreads();  // previous iteration done reading KT/Vs
        for (int i = tid; i < 128 * 32; i += 256) {
            int n = i >> 5, k4 = (i & 31) << 2;   // n = key, k4 = hd
            float4 v = *(const float4*)(Kp + (size_t)(kt * 128 + n) * Cdim + k4);
            KT[k4 + 0][n] = f2tf32(v.x); KT[k4 + 1][n] = f2tf32(v.y);
            KT[k4 + 2][n] = f2tf32(v.z); KT[k4 + 3][n] = f2tf32(v.w);
        }
        for (int i = tid; i < 128 * 32; i += 256) {
            int kr = i >> 5, n4 = (i & 31) << 2;  // kr = key, n4 = hd
            float4 v = *(const float4*)(Vp + (size_t)(kt * 128 + kr) * Cdim + n4);
            Vs[kr][n4 + 0] = f2tf32(v.x); Vs[kr][n4 + 1] = f2tf32(v.y);
            Vs[kr][n4 + 2] = f2tf32(v.z); Vs[kr][n4 + 3] = f2tf32(v.w);
        }
        __syncthreads();

        // ---- S = Q @ K^T : 16 uninterrupted k-steps ----
        float accs[16][4] = {};
#pragma unroll
        for (int kk = 0; kk < 16; kk++) {
            int kg = kk * 8;
            unsigned aq[4];
            aq[0] = Qs[qr + g][kg + tg];
            aq[1] = Qs[qr + g + 8][kg + tg];
            aq[2] = Qs[qr + g][kg + tg + 4];
            aq[3] = Qs[qr + g + 8][kg + tg + 4];
#pragma unroll
            for (int nb = 0; nb < 16; nb++) {
                unsigned bb[2];
                bb[0] = KT[kg + tg][nb * 8 + g];
                bb[1] = KT[kg + tg + 4][nb * 8 + g];
                mma_tf32(accs[nb], aq, bb);
            }
        }

        // ---- scale + causal mask + online softmax ----
        bool diag = (kt == qt);
        int rl0 = qr + g, rl1 = qr + g + 8;    // local row indices
        float mx0 = -1e30f, mx1 = -1e30f;
#pragma unroll
        for (int nb = 0; nb < 16; nb++) {
            int cl = nb * 8 + 2 * tg;          // local col of elems 0/2
            float v0 = accs[nb][0] * SCALE_ATT;
            float v1 = accs[nb][1] * SCALE_ATT;
            float v2 = accs[nb][2] * SCALE_ATT;
            float v3 = accs[nb][3] * SCALE_ATT;
            if (diag) {
                if (cl     > rl0) v0 = -1e30f;
                if (cl + 1 > rl0) v1 = -1e30f;
                if (cl     > rl1) v2 = -1e30f;
                if (cl + 1 > rl1) v3 = -1e30f;
            }
            accs[nb][0] = v0; accs[nb][1] = v1; accs[nb][2] = v2; accs[nb][3] = v3;
            mx0 = fmaxf(mx0, fmaxf(v0, v1));
            mx1 = fmaxf(mx1, fmaxf(v2, v3));
        }
        // quad reduction (lanes sharing g)
        mx0 = fmaxf(mx0, __shfl_xor_sync(FULLM, mx0, 1));
        mx0 = fmaxf(mx0, __shfl_xor_sync(FULLM, mx0, 2));
        mx1 = fmaxf(mx1, __shfl_xor_sync(FULLM, mx1, 1));
        mx1 = fmaxf(mx1, __shfl_xor_sync(FULLM, mx1, 2));

        float mn0 = fmaxf(m0, mx0), mn1 = fmaxf(m1, mx1);
        float sc0 = __expf(m0 - mn0), sc1 = __expf(m1 - mn1);
        m0 = mn0; m1 = mn1;
        float s0 = 0.f, s1 = 0.f;
#pragma unroll
        for (int nb = 0; nb < 16; nb++) {
            float p0 = __expf(accs[nb][0] - mn0);
            float p1 = __expf(accs[nb][1] - mn0);
            float p2 = __expf(accs[nb][2] - mn1);
            float p3 = __expf(accs[nb][3] - mn1);
            s0 += p0 + p1; s1 += p2 + p3;
            // store tf32 bit pattern in-place for PV mma
            accs[nb][0] = __uint_as_float(f2tf32(p0));
            accs[nb][1] = __uint_as_float(f2tf32(p1));
            accs[nb][2] = __uint_as_float(f2tf32(p2));
            accs[nb][3] = __uint_as_float(f2tf32(p3));
        }
        // quad-reduce partial row sums (each thread holds 32 of 128 cols)
        s0 += __shfl_xor_sync(FULLM, s0, 1);
        s0 += __shfl_xor_sync(FULLM, s0, 2);
        s1 += __shfl_xor_sync(FULLM, s1, 1);
        s1 += __shfl_xor_sync(FULLM, s1, 2);
        l0 = l0 * sc0 + s0; l1 = l1 * sc1 + s1;
#pragma unroll
        for (int nb = 0; nb < 16; nb++) {
            acco[nb][0] *= sc0; acco[nb][1] *= sc0;
            acco[nb][2] *= sc1; acco[nb][3] *= sc1;
        }

        // ---- O += P @ V : 16 uninterrupted k-steps ----
#pragma unroll
        for (int kb = 0; kb < 16; kb++) {
            // C-frag -> A-frag permutation via quad shuffles
            float c0 = accs[kb][0], c1 = accs[kb][1];
            float c2 = accs[kb][2], c3 = accs[kb][3];
            int q0 = (lane & ~3) | (tg >> 1);        // owner of col tg
            int q1 = q0 | 2;                          // owner of col tg+4
            bool odd = tg & 1;
            float t00 = __shfl_sync(FULLM, c0, q0), t01 = __shfl_sync(FULLM, c1, q0);
            float t10 = __shfl_sync(FULLM, c2, q0), t11 = __shfl_sync(FULLM, c3, q0);
            float t20 = __shfl_sync(FULLM, c0, q1), t21 = __shfl_sync(FULLM, c1, q1);
            float t30 = __shfl_sync(FULLM, c2, q1), t31 = __shfl_sync(FULLM, c3, q1);
            unsigned ap[4];
            ap[0] = __float_as_uint(odd ? t01 : t00);  // row g,   col tg
            ap[1] = __float_as_uint(odd ? t11 : t10);  // row g+8, col tg
            ap[2] = __float_as_uint(odd ? t21 : t20);  // row g,   col tg+4
            ap[3] = __float_as_uint(odd ? t31 : t30);  // row g+8, col tg+4
            int kg = kb * 8;
#pragma unroll
            for (int nb = 0; nb < 16; nb++) {
                unsigned bb[2];
                bb[0] = Vs[kg + tg][nb * 8 + g];
                bb[1] = Vs[kg + tg + 4][nb * 8 + g];
                mma_tf32(acco[nb], ap, bb);
            }
        }
    }

    // ---- epilogue: O / l ----
    float inv0 = 1.0f / l0, inv1 = 1.0f / l1;
    int r0 = qt * 128 + qr + g, r1 = r0 + 8;
#pragma unroll
    for (int nb = 0; nb < 16; nb++) {
        int cc = nb * 8 + 2 * tg;
        float2 o0 = make_float2(acco[nb][0] * inv0, acco[nb][1] * inv0);
        float2 o1 = make_float2(acco[nb][2] * inv1, acco[nb][3] * inv1);
        *(float2*)(Yp + (size_t)r0 * Cdim + cc) = o0;
        *(float2*)(Yp + (size_t)r1 * Cdim + cc) = o1;
    }
}

// ---------------------------------------------------------------------------
extern "C" void kernel_launch(void* const* d_in, const int* in_sizes, int n_in,
                              void* d_out, int out_size) {
    const float* x    = (const float*)d_in[0];
    const float* diag = (const float*)d_in[1];
    const float* left = (const float*)d_in[2];
    const float* rw   = (const float*)d_in[3];
    const float* rb   = (const float*)d_in[4];
    const float* bp   = (const float*)d_in[5];
    float* out = (float*)d_out;

    float *pt, *pq, *pk, *pv, *py;
    cudaGetSymbolAddress((void**)&pt, g_t);
    cudaGetSymbolAddress((void**)&pq, g_q);
    cudaGetSymbolAddress((void**)&pk, g_k);
    cudaGetSymbolAddress((void**)&pv, g_v);
    cudaGetSymbolAddress((void**)&py, g_y);

    static bool attr_done = false;
    if (!attr_done) {
        cudaFuncSetAttribute(flash_attn, cudaFuncAttributeMaxDynamicSharedMemorySize,
                             FA_SMEM);
        attr_done = true;
    }

    float* dst[3] = {pq, pk, pv};
    for (int i = 0; i < 3; i++) {
        left_proj_mma<<<BT / 128, 256>>>(x, left + (size_t)i * Rr * Cdim, pt);
        fused_out_mma<<<dim3(BT / 128, NB), 256>>>(
            x, pt,
            diag + (size_t)i * NB * BS * BS,
            rw + (size_t)i * Cdim * Rr,
            rb + (size_t)i * Cdim,
            bp + (size_t)i * Cdim,
            dst[i]);
    }

    flash_attn<<<dim3(16, NBH), 256, FA_SMEM>>>(pq, pk, pv, py);

    left_proj_mma<<<BT / 128, 256>>>(py, left + (size_t)3 * Rr * Cdim, pt);
    fused_out_mma<<<dim3(BT / 128, NB), 256>>>(
        py, pt,
        diag + (size_t)3 * NB * BS * BS,
        rw + (size_t)3 * Cdim * Rr,
        rb + (size_t)3 * Cdim,
        bp + (size_t)3 * Cdim,
        out);
}

// round 13
// speedup vs baseline: 2.6933x; 1.9351x over previous
#include <cuda_runtime.h>
#include <math.h>

#define Bb   4
#define Tdim 2048
#define Cdim 2048
#define BT   8192        // Bb*Tdim
#define H    16
#define HD   128
#define Rr   128
#define NB   16
#define BS   128
#define NBH  64          // Bb*H

static const float SCALE_ATT = 0.08838834764831845f; // 1/sqrt(128)
#define FULLM 0xffffffffu

// scratch (device globals: no allocation allowed)
__device__ float g_t[(size_t)3 * BT * Rr];
__device__ float g_qkv[(size_t)3 * Bb * Tdim * Cdim];
__device__ float g_y[(size_t)Bb * Tdim * Cdim];

// ---------------------------------------------------------------------------
// cp.async + tf32 mma helpers (raw fp32 bits fed to HMMA.TF32: truncation)
// ---------------------------------------------------------------------------
__device__ __forceinline__ void cp_async16(void* smem, const void* gmem) {
    unsigned s = (unsigned)__cvta_generic_to_shared(smem);
    asm volatile("cp.async.cg.shared.global [%0], [%1], 16;\n" :: "r"(s), "l"(gmem));
}
#define CP_COMMIT() asm volatile("cp.async.commit_group;\n" ::: "memory")
#define CP_WAIT0()  asm volatile("cp.async.wait_group 0;\n" ::: "memory")
#define CP_WAIT1()  asm volatile("cp.async.wait_group 1;\n" ::: "memory")

__device__ __forceinline__ void mma_tf32(float* c, const unsigned* a, const unsigned* b) {
    asm volatile(
        "mma.sync.aligned.m16n8k8.row.col.f32.tf32.tf32.f32 "
        "{%0,%1,%2,%3}, {%4,%5,%6,%7}, {%8,%9}, {%0,%1,%2,%3};\n"
        : "+f"(c[0]), "+f"(c[1]), "+f"(c[2]), "+f"(c[3])
        : "r"(a[0]), "r"(a[1]), "r"(a[2]), "r"(a[3]), "r"(b[0]), "r"(b[1]));
}
__device__ __forceinline__ unsigned ldu(const float* p) { return __float_as_uint(*p); }

// ---------------------------------------------------------------------------
// GEMM building blocks: 128x128 block tile, 8 warps (wm in 0..1, wn in 0..3),
// BK=32.
//   nk layout: 128 rows x 32 k, LD 36  (36 mod 32 = 4  -> frag addr 4g+tg, distinct)
//   kn layout: 32 k-rows x 128 n, LD 136 (136 mod 32 = 8 -> frag addr 8tg+g, distinct)
// ROUND-12 FIX: kn LD was 40 (rows of 128 floats overlapped!). Must be >=128.
// ---------------------------------------------------------------------------
#define GS   4608          // floats per stage region (128*36); kn needs 32*136=4352
#define KNLD 136

// 128 rows x 32 k from row-major src (ld = row stride)
__device__ __forceinline__ void cpa_128x32(float* S, const float* A, int ld, int tid) {
#pragma unroll
    for (int p = 0; p < 4; p++) {
        int idx = tid + p * 256;
        int row = idx >> 3, c4 = (idx & 7) << 2;
        cp_async16(S + row * 36 + c4, A + (size_t)row * ld + c4);
    }
}
// 32 k-rows x 128 n from [k][n] src
__device__ __forceinline__ void cpa_32x128(float* S, const float* B, int ld, int tid) {
#pragma unroll
    for (int p = 0; p < 4; p++) {
        int idx = tid + p * 256;
        int kr = idx >> 5, n4 = (idx & 31) << 2;
        cp_async16(S + kr * KNLD + n4, B + (size_t)kr * ld + n4);
    }
}

// one BK=32 step; B in nk layout [n][36]
__device__ __forceinline__ void mma_step_nk(const float* As, const float* Bs,
                                            int wm, int wn, int lane, float acc[4][4][4]) {
    int g = lane >> 2, tg = lane & 3;
#pragma unroll
    for (int kk = 0; kk < 4; kk++) {
        int k = kk * 8;
        unsigned a[4][4], b[4][2];
#pragma unroll
        for (int im = 0; im < 4; im++) {
            const float* r0 = As + (wm * 64 + im * 16 + g) * 36;
            a[im][0] = ldu(r0 + k + tg);
            a[im][1] = ldu(r0 + 8 * 36 + k + tg);
            a[im][2] = ldu(r0 + k + tg + 4);
            a[im][3] = ldu(r0 + 8 * 36 + k + tg + 4);
        }
#pragma unroll
        for (int jn = 0; jn < 4; jn++) {
            const float* rn = Bs + (wn * 32 + jn * 8 + g) * 36;
            b[jn][0] = ldu(rn + k + tg);
            b[jn][1] = ldu(rn + k + tg + 4);
        }
#pragma unroll
        for (int im = 0; im < 4; im++)
#pragma unroll
            for (int jn = 0; jn < 4; jn++) mma_tf32(acc[im][jn], a[im], b[jn]);
    }
}
// one BK=32 step; B in kn layout [k][KNLD]
__device__ __forceinline__ void mma_step_kn(const float* As, const float* Bs,
                                            int wm, int wn, int lane, float acc[4][4][4]) {
    int g = lane >> 2, tg = lane & 3;
#pragma unroll
    for (int kk = 0; kk < 4; kk++) {
        int k = kk * 8;
        unsigned a[4][4], b[4][2];
#pragma unroll
        for (int im = 0; im < 4; im++) {
            const float* r0 = As + (wm * 64 + im * 16 + g) * 36;
            a[im][0] = ldu(r0 + k + tg);
            a[im][1] = ldu(r0 + 8 * 36 + k + tg);
            a[im][2] = ldu(r0 + k + tg + 4);
            a[im][3] = ldu(r0 + 8 * 36 + k + tg + 4);
        }
#pragma unroll
        for (int jn = 0; jn < 4; jn++) {
            int nb = wn * 32 + jn * 8 + g;
            b[jn][0] = ldu(Bs + (k + tg) * KNLD + nb);
            b[jn][1] = ldu(Bs + (k + tg + 4) * KNLD + nb);
        }
#pragma unroll
        for (int im = 0; im < 4; im++)
#pragma unroll
            for (int jn = 0; jn < 4; jn++) mma_tf32(acc[im][jn], a[im], b[jn]);
    }
}

#define GEMM_SMEM (4 * GS * 4)   // 2 A stages + 2 B stages = 73728 B

// ---------------------------------------------------------------------------
// K1: t_y = X @ L_y^T   grid (BT/128, nProj); L_y = L + y*Lstride
// ---------------------------------------------------------------------------
__global__ __launch_bounds__(256, 2) void left_proj_mma(
    const float* __restrict__ X, const float* __restrict__ L, size_t Lstride,
    float* __restrict__ Tout, size_t Tstride) {
    extern __shared__ float gsm[];
    float* Aab = gsm;
    float* Bab = gsm + 2 * GS;
    int tid = threadIdx.x, lane = tid & 31, w = tid >> 5, wm = w >> 2, wn = w & 3;
    int m0 = blockIdx.x * 128;
    const float* Lp = L + blockIdx.y * Lstride;
    float* Tp = Tout + blockIdx.y * Tstride;
    float acc[4][4][4] = {};

    cpa_128x32(Aab, X + (size_t)m0 * Cdim, Cdim, tid);
    cpa_128x32(Bab, Lp, Cdim, tid);
    CP_COMMIT();
    const int NS = Cdim / 32;
    for (int s = 0; s < NS; s++) {
        int st = s & 1;
        CP_WAIT0();
        __syncthreads();
        if (s + 1 < NS) {
            int nt = st ^ 1;
            cpa_128x32(Aab + nt * GS, X + (size_t)m0 * Cdim + (s + 1) * 32, Cdim, tid);
            cpa_128x32(Bab + nt * GS, Lp + (s + 1) * 32, Cdim, tid);
            CP_COMMIT();
        }
        mma_step_nk(Aab + st * GS, Bab + st * GS, wm, wn, lane, acc);
        __syncthreads();
    }
    int g = lane >> 2, tg = lane & 3;
#pragma unroll
    for (int im = 0; im < 4; im++)
#pragma unroll
        for (int jn = 0; jn < 4; jn++) {
            int r = m0 + wm * 64 + im * 16 + g;
            int c = wn * 32 + jn * 8 + tg * 2;
            Tp[(size_t)r * Rr + c]           = acc[im][jn][0];
            Tp[(size_t)r * Rr + c + 1]       = acc[im][jn][1];
            Tp[(size_t)(r + 8) * Rr + c]     = acc[im][jn][2];
            Tp[(size_t)(r + 8) * Rr + c + 1] = acc[im][jn][3];
        }
}

// ---------------------------------------------------------------------------
// K2: fused LORI output.  grid (BT/128, NB, nProj); z strides select layer.
// ---------------------------------------------------------------------------
__global__ __launch_bounds__(256, 2) void fused_out_mma(
    const float* __restrict__ X,
    const float* __restrict__ Tl, size_t Tstride,
    const float* __restrict__ Dg, size_t Dstride,
    const float* __restrict__ RW, size_t RWstride,
    const float* __restrict__ rb,
    const float* __restrict__ bp, size_t Bstride,
    float* __restrict__ Y, size_t Ystride) {
    extern __shared__ float gsm[];
    float* Aab = gsm;
    float* Bab = gsm + 2 * GS;
    int tid = threadIdx.x, lane = tid & 31, w = tid >> 5, wm = w >> 2, wn = w & 3;
    int m0 = blockIdx.x * 128;
    int c0 = blockIdx.y * BS;
    int z = blockIdx.z;
    const float* Tlp = Tl + z * Tstride;
    const float* D   = Dg + z * Dstride + (size_t)blockIdx.y * BS * BS;
    const float* RWp = RW + z * RWstride;
    const float* rbp = rb + z * Bstride;
    const float* bpp = bp + z * Bstride;
    float* Yp        = Y  + z * Ystride;
    float acc[4][4][4] = {};

    // 8 steps: 0..3 blockdiag (B kn), 4..7 low-rank (B nk)
    cpa_128x32(Aab, X + (size_t)m0 * Cdim + c0, Cdim, tid);
    cpa_32x128(Bab, D, BS, tid);
    CP_COMMIT();
    for (int s = 0; s < 8; s++) {
        int st = s & 1;
        CP_WAIT0();
        __syncthreads();
        if (s + 1 < 8) {
            int nt = st ^ 1, s1 = s + 1;
            if (s1 < 4) {
                cpa_128x32(Aab + nt * GS, X + (size_t)m0 * Cdim + c0 + s1 * 32, Cdim, tid);
                cpa_32x128(Bab + nt * GS, D + (size_t)(s1 * 32) * BS, BS, tid);
            } else {
                cpa_128x32(Aab + nt * GS, Tlp + (size_t)m0 * Rr + (s1 - 4) * 32, Rr, tid);
                cpa_128x32(Bab + nt * GS, RWp + (size_t)c0 * Rr + (s1 - 4) * 32, Rr, tid);
            }
            CP_COMMIT();
        }
        if (s < 4) mma_step_kn(Aab + st * GS, Bab + st * GS, wm, wn, lane, acc);
        else       mma_step_nk(Aab + st * GS, Bab + st * GS, wm, wn, lane, acc);
        __syncthreads();
    }

    int g = lane >> 2, tg = lane & 3;
#pragma unroll
    for (int im = 0; im < 4; im++)
#pragma unroll
        for (int jn = 0; jn < 4; jn++) {
            int r = m0 + wm * 64 + im * 16 + g;
            int c = c0 + wn * 32 + jn * 8 + tg * 2;
            float b0 = rbp[c] + bpp[c], b1 = rbp[c + 1] + bpp[c + 1];
            Yp[(size_t)r * Cdim + c]           = acc[im][jn][0] + b0;
            Yp[(size_t)r * Cdim + c + 1]       = acc[im][jn][1] + b1;
            Yp[(size_t)(r + 8) * Cdim + c]     = acc[im][jn][2] + b0;
            Yp[(size_t)(r + 8) * Cdim + c + 1] = acc[im][jn][3] + b1;
        }
}

// ---------------------------------------------------------------------------
// K3: fused flash attention. grid (qt=16, bh=64), 8 warps.
// smem: Qs[128][132], Ks[128][132] (key rows, hd contig), Vs[128][136].
// cp.async pipeline: K_{t+1} loads during softmax/PV, V_{t+1} during S_{t+1}.
// Last-iter edge case: no K-prefetch behind V_qt -> must use wait_group 0.
// ---------------------------------------------------------------------------
#define QLD 132
#define KLD 132
#define VLD 136
#define FA_SMEM ((128 * QLD + 128 * KLD + 128 * VLD) * 4)

__global__ __launch_bounds__(256) void flash_attn(const float* __restrict__ Q,
                                                  const float* __restrict__ Kg,
                                                  const float* __restrict__ Vg,
                                                  float* __restrict__ Y) {
    extern __shared__ float fsm[];
    float* Qs = fsm;                         // [q][hd]
    float* Ks = fsm + 128 * QLD;             // [key][hd]
    float* Vs = fsm + 128 * QLD + 128 * KLD; // [key][hd]

    int qt = gridDim.x - 1 - blockIdx.x;   // big q-tiles first
    int bh = blockIdx.y;
    int b = bh / H, h = bh % H;
    const float* Qp = Q  + (size_t)b * Tdim * Cdim + (size_t)h * HD;
    const float* Kp = Kg + (size_t)b * Tdim * Cdim + (size_t)h * HD;
    const float* Vp = Vg + (size_t)b * Tdim * Cdim + (size_t)h * HD;
    float* Yp       = Y  + (size_t)b * Tdim * Cdim + (size_t)h * HD;

    int tid = threadIdx.x, lane = tid & 31, w = tid >> 5;
    int g = lane >> 2, tg = lane & 3;
    int qr = w * 16;

    // preload Q + K0 (group), then V0 (group)
#pragma unroll
    for (int p = 0; p < 16; p++) {
        int idx = tid + p * 256;
        int row = idx >> 5, c4 = (idx & 31) << 2;
        cp_async16(Qs + row * QLD + c4, Qp + (size_t)(qt * 128 + row) * Cdim + c4);
    }
#pragma unroll
    for (int p = 0; p < 16; p++) {
        int idx = tid + p * 256;
        int row = idx >> 5, c4 = (idx & 31) << 2;
        cp_async16(Ks + row * KLD + c4, Kp + (size_t)row * Cdim + c4);
    }
    CP_COMMIT();
#pragma unroll
    for (int p = 0; p < 16; p++) {
        int idx = tid + p * 256;
        int row = idx >> 5, c4 = (idx & 31) << 2;
        cp_async16(Vs + row * VLD + c4, Vp + (size_t)row * Cdim + c4);
    }
    CP_COMMIT();

    float acco[16][4] = {};
    float m0 = -1e30f, m1 = -1e30f;
    float l0 = 0.f, l1 = 0.f;

    for (int kt = 0; kt <= qt; kt++) {
        CP_WAIT1();          // Q+K_kt resident (V group may still fly)
        __syncthreads();

        // ---- S = Q @ K^T ----
        float accs[16][4] = {};
#pragma unroll
        for (int kk = 0; kk < 16; kk++) {
            int kg = kk * 8;
            unsigned aq[4];
            const float* q0 = Qs + (qr + g) * QLD;
            aq[0] = ldu(q0 + kg + tg);
            aq[1] = ldu(q0 + 8 * QLD + kg + tg);
            aq[2] = ldu(q0 + kg + tg + 4);
            aq[3] = ldu(q0 + 8 * QLD + kg + tg + 4);
#pragma unroll
            for (int nb = 0; nb < 16; nb++) {
                unsigned bb[2];
                const float* kr = Ks + (nb * 8 + g) * KLD;
                bb[0] = ldu(kr + kg + tg);
                bb[1] = ldu(kr + kg + tg + 4);
                mma_tf32(accs[nb], aq, bb);
            }
        }
        __syncthreads();     // all warps done reading Ks
        if (kt < qt) {       // prefetch K_{kt+1} (overlaps softmax + PV)
#pragma unroll
            for (int p = 0; p < 16; p++) {
                int idx = tid + p * 256;
                int row = idx >> 5, c4 = (idx & 31) << 2;
                cp_async16(Ks + row * KLD + c4,
                           Kp + (size_t)((kt + 1) * 128 + row) * Cdim + c4);
            }
            CP_COMMIT();
        }

        // ---- scale + causal mask + online softmax ----
        bool diag = (kt == qt);
        int rl0 = qr + g, rl1 = qr + g + 8;
        float mx0 = -1e30f, mx1 = -1e30f;
#pragma unroll
        for (int nb = 0; nb < 16; nb++) {
            int cl = nb * 8 + 2 * tg;
            float v0 = accs[nb][0] * SCALE_ATT;
            float v1 = accs[nb][1] * SCALE_ATT;
            float v2 = accs[nb][2] * SCALE_ATT;
            float v3 = accs[nb][3] * SCALE_ATT;
            if (diag) {
                if (cl     > rl0) v0 = -1e30f;
                if (cl + 1 > rl0) v1 = -1e30f;
                if (cl     > rl1) v2 = -1e30f;
                if (cl + 1 > rl1) v3 = -1e30f;
            }
            accs[nb][0] = v0; accs[nb][1] = v1; accs[nb][2] = v2; accs[nb][3] = v3;
            mx0 = fmaxf(mx0, fmaxf(v0, v1));
            mx1 = fmaxf(mx1, fmaxf(v2, v3));
        }
        mx0 = fmaxf(mx0, __shfl_xor_sync(FULLM, mx0, 1));
        mx0 = fmaxf(mx0, __shfl_xor_sync(FULLM, mx0, 2));
        mx1 = fmaxf(mx1, __shfl_xor_sync(FULLM, mx1, 1));
        mx1 = fmaxf(mx1, __shfl_xor_sync(FULLM, mx1, 2));

        float mn0 = fmaxf(m0, mx0), mn1 = fmaxf(m1, mx1);
        float sc0 = __expf(m0 - mn0), sc1 = __expf(m1 - mn1);
        m0 = mn0; m1 = mn1;
        float s0 = 0.f, s1 = 0.f;
#pragma unroll
        for (int nb = 0; nb < 16; nb++) {
            float p0 = __expf(accs[nb][0] - mn0);
            float p1 = __expf(accs[nb][1] - mn0);
            float p2 = __expf(accs[nb][2] - mn1);
            float p3 = __expf(accs[nb][3] - mn1);
            s0 += p0 + p1; s1 += p2 + p3;
            accs[nb][0] = p0; accs[nb][1] = p1; accs[nb][2] = p2; accs[nb][3] = p3;
        }
        s0 += __shfl_xor_sync(FULLM, s0, 1);
        s0 += __shfl_xor_sync(FULLM, s0, 2);
        s1 += __shfl_xor_sync(FULLM, s1, 1);
        s1 += __shfl_xor_sync(FULLM, s1, 2);
        l0 = l0 * sc0 + s0; l1 = l1 * sc1 + s1;
#pragma unroll
        for (int nb = 0; nb < 16; nb++) {
            acco[nb][0] *= sc0; acco[nb][1] *= sc0;
            acco[nb][2] *= sc1; acco[nb][3] *= sc1;
        }

        // V_kt must be resident. Normal iters: pending = {V_kt, K_{kt+1}} ->
        // wait_group 1 drains V_kt. Last iter: pending = {V_qt} only.
        if (kt < qt) CP_WAIT1(); else CP_WAIT0();
        __syncthreads();

        // ---- O += P @ V ----
#pragma unroll
        for (int kb = 0; kb < 16; kb++) {
            float c0 = accs[kb][0], c1 = accs[kb][1];
            float c2 = accs[kb][2], c3 = accs[kb][3];
            int q0 = (lane & ~3) | (tg >> 1);
            int q1 = q0 | 2;
            bool odd = tg & 1;
            float t00 = __shfl_sync(FULLM, c0, q0), t01 = __shfl_sync(FULLM, c1, q0);
            float t10 = __shfl_sync(FULLM, c2, q0), t11 = __shfl_sync(FULLM, c3, q0);
            float t20 = __shfl_sync(FULLM, c0, q1), t21 = __shfl_sync(FULLM, c1, q1);
            float t30 = __shfl_sync(FULLM, c2, q1), t31 = __shfl_sync(FULLM, c3, q1);
            unsigned ap[4];
            ap[0] = __float_as_uint(odd ? t01 : t00);
            ap[1] = __float_as_uint(odd ? t11 : t10);
            ap[2] = __float_as_uint(odd ? t21 : t20);
            ap[3] = __float_as_uint(odd ? t31 : t30);
            int kg = kb * 8;
#pragma unroll
            for (int nb = 0; nb < 16; nb++) {
                unsigned bb[2];
                bb[0] = ldu(Vs + (kg + tg) * VLD + nb * 8 + g);
                bb[1] = ldu(Vs + (kg + tg + 4) * VLD + nb * 8 + g);
                mma_tf32(acco[nb], ap, bb);
            }
        }
        __syncthreads();     // all warps done reading Vs
        if (kt < qt) {       // prefetch V_{kt+1} (overlaps next S)
#pragma unroll
            for (int p = 0; p < 16; p++) {
                int idx = tid + p * 256;
                int row = idx >> 5, c4 = (idx & 31) << 2;
                cp_async16(Vs + row * VLD + c4,
                           Vp + (size_t)((kt + 1) * 128 + row) * Cdim + c4);
            }
            CP_COMMIT();
        }
    }

    // ---- epilogue: O / l ----
    float inv0 = 1.0f / l0, inv1 = 1.0f / l1;
    int r0 = qt * 128 + qr + g, r1 = r0 + 8;
#pragma unroll
    for (int nb = 0; nb < 16; nb++) {
        int cc = nb * 8 + 2 * tg;
        float2 o0 = make_float2(acco[nb][0] * inv0, acco[nb][1] * inv0);
        float2 o1 = make_float2(acco[nb][2] * inv1, acco[nb][3] * inv1);
        *(float2*)(Yp + (size_t)r0 * Cdim + cc) = o0;
        *(float2*)(Yp + (size_t)r1 * Cdim + cc) = o1;
    }
}

// ---------------------------------------------------------------------------
extern "C" void kernel_launch(void* const* d_in, const int* in_sizes, int n_in,
                              void* d_out, int out_size) {
    const float* x    = (const float*)d_in[0];
    const float* diag = (const float*)d_in[1];
    const float* left = (const float*)d_in[2];
    const float* rw   = (const float*)d_in[3];
    const float* rb   = (const float*)d_in[4];
    const float* bp   = (const float*)d_in[5];
    float* out = (float*)d_out;

    float *pt, *pqkv, *py;
    cudaGetSymbolAddress((void**)&pt, g_t);
    cudaGetSymbolAddress((void**)&pqkv, g_qkv);
    cudaGetSymbolAddress((void**)&py, g_y);

    static bool attr_done = false;
    if (!attr_done) {
        cudaFuncSetAttribute(flash_attn, cudaFuncAttributeMaxDynamicSharedMemorySize, FA_SMEM);
        cudaFuncSetAttribute(left_proj_mma, cudaFuncAttributeMaxDynamicSharedMemorySize, GEMM_SMEM);
        cudaFuncSetAttribute(fused_out_mma, cudaFuncAttributeMaxDynamicSharedMemorySize, GEMM_SMEM);
        attr_done = true;
    }

    const size_t PC = (size_t)BT * Cdim;   // activation plane
    const size_t PT = (size_t)BT * Rr;     // t plane

    // q,k,v left-proj in one launch (grid.y = 3)
    left_proj_mma<<<dim3(BT / 128, 3), 256, GEMM_SMEM>>>(
        x, left, (size_t)Rr * Cdim, pt, PT);
    // q,k,v fused output in one launch (grid.z = 3)
    fused_out_mma<<<dim3(BT / 128, NB, 3), 256, GEMM_SMEM>>>(
        x,
        pt, PT,
        diag, (size_t)NB * BS * BS,
        rw, (size_t)Cdim * Rr,
        rb, bp, (size_t)Cdim,
        pqkv, PC);

    flash_attn<<<dim3(16, NBH), 256, FA_SMEM>>>(pqkv, pqkv + PC, pqkv + 2 * PC, py);

    // output projection (single layer: strides 0)
    left_proj_mma<<<dim3(BT / 128, 1), 256, GEMM_SMEM>>>(
        py, left + (size_t)3 * Rr * Cdim, 0, pt, 0);
    fused_out_mma<<<dim3(BT / 128, NB, 1), 256, GEMM_SMEM>>>(
        py,
        pt, 0,
        diag + (size_t)3 * NB * BS * BS, 0,
        rw + (size_t)3 * Cdim * Rr, 0,
        rb + (size_t)3 * Cdim, bp + (size_t)3 * Cdim, 0,
        out, PC);
}